// round 1
// baseline (speedup 1.0000x reference)
#include <cuda_runtime.h>
#include <cstdint>
#include <cstddef>

#define NUM_B   8
#define NUM_N   1024
#define NUM_H   8
#define DHEAD   64
#define DIN     512
#define DINNER  512
#define DOUT    512
#define QK_SCALE 0.125f
#define NEG_BIG (-1.0e30f)

// Scratch (allocation-free: device globals)
__device__ float g_q[NUM_B * NUM_H * NUM_N * DHEAD];
__device__ float g_k[NUM_B * NUM_H * NUM_N * DHEAD];
__device__ float g_v[NUM_B * NUM_H * NUM_N * DHEAD];
__device__ float g_att[NUM_B * NUM_N * DINNER];

// ---------------------------------------------------------------------------
// Kernel 1: fused QKV projection.  C[8192 x 1536] = x[8192 x 512] @ [Wq | Wkv]
// 64x64 tile, BK=16, 256 threads, 4x4 micro-tile. Epilogue scatters into
// q/k/v with [b,h,n,d] layout.
// ---------------------------------------------------------------------------
__global__ __launch_bounds__(256) void qkv_gemm_kernel(
    const float* __restrict__ x,
    const float* __restrict__ Wq,
    const float* __restrict__ Wkv)
{
    __shared__ float As[64][17];
    __shared__ float Bs[16][68];

    const int tid  = threadIdx.x;
    const int tx   = tid & 15, ty = tid >> 4;
    const int row0 = blockIdx.y * 64;
    const int col0 = blockIdx.x * 64;

    const float* W; int wld, wc0;
    if (col0 < DINNER) { W = Wq;  wld = DINNER;     wc0 = col0; }
    else               { W = Wkv; wld = 2 * DINNER; wc0 = col0 - DINNER; }

    const int ar = tid >> 2, ac = (tid & 3) * 4;
    const int br = tid >> 4, bc = (tid & 15) * 4;

    float acc[4][4];
#pragma unroll
    for (int i = 0; i < 4; i++)
#pragma unroll
        for (int j = 0; j < 4; j++) acc[i][j] = 0.f;

    for (int k0 = 0; k0 < DIN; k0 += 16) {
        float4 a4 = *reinterpret_cast<const float4*>(x + (size_t)(row0 + ar) * DIN + k0 + ac);
        As[ar][ac + 0] = a4.x; As[ar][ac + 1] = a4.y;
        As[ar][ac + 2] = a4.z; As[ar][ac + 3] = a4.w;
        float4 b4 = *reinterpret_cast<const float4*>(W + (size_t)(k0 + br) * wld + wc0 + bc);
        Bs[br][bc + 0] = b4.x; Bs[br][bc + 1] = b4.y;
        Bs[br][bc + 2] = b4.z; Bs[br][bc + 3] = b4.w;
        __syncthreads();

#pragma unroll
        for (int kk = 0; kk < 16; kk++) {
            float a[4], b[4];
#pragma unroll
            for (int i = 0; i < 4; i++) a[i] = As[ty * 4 + i][kk];
#pragma unroll
            for (int j = 0; j < 4; j++) b[j] = Bs[kk][tx * 4 + j];
#pragma unroll
            for (int i = 0; i < 4; i++)
#pragma unroll
                for (int j = 0; j < 4; j++) acc[i][j] += a[i] * b[j];
        }
        __syncthreads();
    }

#pragma unroll
    for (int i = 0; i < 4; i++) {
        const int r  = row0 + ty * 4 + i;
        const int bb = r >> 10, n = r & 1023;
#pragma unroll
        for (int j = 0; j < 4; j++) {
            const int c = col0 + tx * 4 + j;
            float* dst; int cc;
            if (c < DINNER)          { dst = g_q; cc = c; }
            else if (c < 2 * DINNER) { dst = g_k; cc = c - DINNER; }
            else                     { dst = g_v; cc = c - 2 * DINNER; }
            const int h = cc >> 6, d = cc & 63;
            dst[((size_t)(bb * NUM_H + h) * NUM_N + n) * DHEAD + d] = acc[i][j];
        }
    }
}

// ---------------------------------------------------------------------------
// Kernel 2: flash attention.  CTA = (h, i-block of 64 rows, b).
// Online softmax; additive -1e30 for masked keys (equivalent to finfo.min).
// Warp owns 8 query rows; lane (lr,ljg): rows r0+lr and r0+lr+4, j-chunk ljg.
// ---------------------------------------------------------------------------
__global__ __launch_bounds__(256) void attn_kernel(
    const float* __restrict__ sim_bias,
    const int*   __restrict__ mask)
{
    extern __shared__ float sm[];
    float* q_s  = sm;                 // 64*65
    float* k_s  = q_s + 64 * 65;      // 64*65
    float* v_s  = k_s + 64 * 65;      // 64*64 (unpadded, float4 stores)
    float* p_s  = v_s + 64 * 64;      // 64*65
    float* mk_s = p_s + 64 * 65;      // 64

    const int h  = blockIdx.x;
    const int i0 = blockIdx.y * 64;
    const int b  = blockIdx.z;
    const int tid = threadIdx.x;

    const float* qg = g_q + ((size_t)(b * NUM_H + h) * NUM_N + i0) * DHEAD;
    const float* kg = g_k + (size_t)(b * NUM_H + h) * NUM_N * DHEAD;
    const float* vg = g_v + (size_t)(b * NUM_H + h) * NUM_N * DHEAD;

    // load q tile (64x64) into padded smem
    {
        const int r = tid >> 2, cb = (tid & 3) * 16;
#pragma unroll
        for (int u = 0; u < 4; u++) {
            float4 t = *reinterpret_cast<const float4*>(qg + (size_t)r * 64 + cb + u * 4);
            q_s[r * 65 + cb + u * 4 + 0] = t.x;
            q_s[r * 65 + cb + u * 4 + 1] = t.y;
            q_s[r * 65 + cb + u * 4 + 2] = t.z;
            q_s[r * 65 + cb + u * 4 + 3] = t.w;
        }
    }

    const int lane = tid & 31;
    const int lr   = lane >> 3;       // 0..3
    const int ljg  = lane & 7;        // 0..7
    const int r0   = (tid >> 5) * 8;  // warp row base
    const int rowA = r0 + lr;
    const int rowB = r0 + lr + 4;

    float m0 = NEG_BIG, m1 = NEG_BIG;
    float l0 = 0.f, l1 = 0.f;
    float o[2][8];
#pragma unroll
    for (int dd = 0; dd < 8; dd++) { o[0][dd] = 0.f; o[1][dd] = 0.f; }

    for (int jt = 0; jt < 16; jt++) {
        const int j0 = jt * 64;
        // cooperative load of k (padded) and v (unpadded) tiles
        {
            const int r = tid >> 2, cb = (tid & 3) * 16;
#pragma unroll
            for (int u = 0; u < 4; u++) {
                float4 t = *reinterpret_cast<const float4*>(kg + (size_t)(j0 + r) * 64 + cb + u * 4);
                k_s[r * 65 + cb + u * 4 + 0] = t.x;
                k_s[r * 65 + cb + u * 4 + 1] = t.y;
                k_s[r * 65 + cb + u * 4 + 2] = t.z;
                k_s[r * 65 + cb + u * 4 + 3] = t.w;
                float4 tv = *reinterpret_cast<const float4*>(vg + (size_t)(j0 + r) * 64 + cb + u * 4);
                *reinterpret_cast<float4*>(&v_s[r * 64 + cb + u * 4]) = tv;
            }
        }
        if (tid < 64) mk_s[tid] = mask[b * NUM_N + j0 + tid] ? 0.f : NEG_BIG;
        __syncthreads();

        // S = q @ k^T for this warp's 8x64 score tile
        float s0[8], s1[8];
#pragma unroll
        for (int jj = 0; jj < 8; jj++) { s0[jj] = 0.f; s1[jj] = 0.f; }
        for (int kk = 0; kk < 64; kk++) {
            const float qa = q_s[rowA * 65 + kk];
            const float qb = q_s[rowB * 65 + kk];
#pragma unroll
            for (int jj = 0; jj < 8; jj++) {
                const float kv = k_s[(ljg * 8 + jj) * 65 + kk];
                s0[jj] += qa * kv;
                s1[jj] += qb * kv;
            }
        }

        // scale + bias + mask; bias layout [b, i, j, h]
        const float* bA = sim_bias + (((size_t)b * NUM_N + (i0 + rowA)) * NUM_N + (j0 + ljg * 8)) * NUM_H + h;
        const float* bB = sim_bias + (((size_t)b * NUM_N + (i0 + rowB)) * NUM_N + (j0 + ljg * 8)) * NUM_H + h;
        float mt0 = NEG_BIG, mt1 = NEG_BIG;
#pragma unroll
        for (int jj = 0; jj < 8; jj++) {
            const float mm = mk_s[ljg * 8 + jj];
            s0[jj] = s0[jj] * QK_SCALE + __ldg(bA + jj * NUM_H) + mm;
            s1[jj] = s1[jj] * QK_SCALE + __ldg(bB + jj * NUM_H) + mm;
            mt0 = fmaxf(mt0, s0[jj]);
            mt1 = fmaxf(mt1, s1[jj]);
        }
#pragma unroll
        for (int off = 1; off < 8; off <<= 1) {
            mt0 = fmaxf(mt0, __shfl_xor_sync(0xffffffffu, mt0, off));
            mt1 = fmaxf(mt1, __shfl_xor_sync(0xffffffffu, mt1, off));
        }

        const float mn0 = fmaxf(m0, mt0), mn1 = fmaxf(m1, mt1);
        const float c0  = __expf(m0 - mn0), c1 = __expf(m1 - mn1);
        l0 *= c0; l1 *= c1;
#pragma unroll
        for (int dd = 0; dd < 8; dd++) { o[0][dd] *= c0; o[1][dd] *= c1; }

        float rs0 = 0.f, rs1 = 0.f;
#pragma unroll
        for (int jj = 0; jj < 8; jj++) {
            const float p0 = __expf(s0[jj] - mn0);
            const float p1 = __expf(s1[jj] - mn1);
            p_s[rowA * 65 + ljg * 8 + jj] = p0;
            p_s[rowB * 65 + ljg * 8 + jj] = p1;
            rs0 += p0; rs1 += p1;
        }
#pragma unroll
        for (int off = 1; off < 8; off <<= 1) {
            rs0 += __shfl_xor_sync(0xffffffffu, rs0, off);
            rs1 += __shfl_xor_sync(0xffffffffu, rs1, off);
        }
        l0 += rs0; l1 += rs1; m0 = mn0; m1 = mn1;
        __syncwarp();

        // O += P @ V   (lane owns d = dd*8 + ljg)
        for (int j = 0; j < 64; j++) {
            const float pa = p_s[rowA * 65 + j];
            const float pb = p_s[rowB * 65 + j];
#pragma unroll
            for (int dd = 0; dd < 8; dd++) {
                const float vv = v_s[j * 64 + dd * 8 + ljg];
                o[0][dd] += pa * vv;
                o[1][dd] += pb * vv;
            }
        }
        __syncthreads();
    }

    const float inv0 = 1.f / l0, inv1 = 1.f / l1;
    float* oA = g_att + ((size_t)b * NUM_N + i0 + rowA) * DINNER + h * DHEAD;
    float* oB = g_att + ((size_t)b * NUM_N + i0 + rowB) * DINNER + h * DHEAD;
#pragma unroll
    for (int dd = 0; dd < 8; dd++) {
        oA[dd * 8 + ljg] = o[0][dd] * inv0;
        oB[dd * 8 + ljg] = o[1][dd] * inv1;
    }
}

// ---------------------------------------------------------------------------
// Kernel 3: output projection.  out[8192 x 512] = att @ Wout + bout
// ---------------------------------------------------------------------------
__global__ __launch_bounds__(256) void out_gemm_kernel(
    const float* __restrict__ Wout,
    const float* __restrict__ bout,
    float* __restrict__ out)
{
    __shared__ float As[64][17];
    __shared__ float Bs[16][68];

    const int tid  = threadIdx.x;
    const int tx   = tid & 15, ty = tid >> 4;
    const int row0 = blockIdx.y * 64;
    const int col0 = blockIdx.x * 64;

    const int ar = tid >> 2, ac = (tid & 3) * 4;
    const int br = tid >> 4, bc = (tid & 15) * 4;

    float acc[4][4];
#pragma unroll
    for (int i = 0; i < 4; i++)
#pragma unroll
        for (int j = 0; j < 4; j++) acc[i][j] = 0.f;

    for (int k0 = 0; k0 < DINNER; k0 += 16) {
        float4 a4 = *reinterpret_cast<const float4*>(g_att + (size_t)(row0 + ar) * DINNER + k0 + ac);
        As[ar][ac + 0] = a4.x; As[ar][ac + 1] = a4.y;
        As[ar][ac + 2] = a4.z; As[ar][ac + 3] = a4.w;
        float4 b4 = *reinterpret_cast<const float4*>(Wout + (size_t)(k0 + br) * DOUT + col0 + bc);
        Bs[br][bc + 0] = b4.x; Bs[br][bc + 1] = b4.y;
        Bs[br][bc + 2] = b4.z; Bs[br][bc + 3] = b4.w;
        __syncthreads();

#pragma unroll
        for (int kk = 0; kk < 16; kk++) {
            float a[4], b[4];
#pragma unroll
            for (int i = 0; i < 4; i++) a[i] = As[ty * 4 + i][kk];
#pragma unroll
            for (int j = 0; j < 4; j++) b[j] = Bs[kk][tx * 4 + j];
#pragma unroll
            for (int i = 0; i < 4; i++)
#pragma unroll
                for (int j = 0; j < 4; j++) acc[i][j] += a[i] * b[j];
        }
        __syncthreads();
    }

#pragma unroll
    for (int i = 0; i < 4; i++) {
        const int r = row0 + ty * 4 + i;
#pragma unroll
        for (int j = 0; j < 4; j++) {
            const int c = col0 + tx * 4 + j;
            out[(size_t)r * DOUT + c] = acc[i][j] + bout[c];
        }
    }
}

// ---------------------------------------------------------------------------
extern "C" void kernel_launch(void* const* d_in, const int* in_sizes, int n_in,
                              void* d_out, int out_size)
{
    const float* x    = (const float*)d_in[0];
    const int*   mask = (const int*)  d_in[1];
    const float* sb   = (const float*)d_in[2];
    const float* Wq   = (const float*)d_in[3];
    const float* Wkv  = (const float*)d_in[4];
    const float* Wout = (const float*)d_in[5];
    const float* bout = (const float*)d_in[6];
    float* out = (float*)d_out;

    // 1) QKV projection: 8192 x 1536
    qkv_gemm_kernel<<<dim3(24, 128), 256>>>(x, Wq, Wkv);

    // 2) flash attention; h fastest in grid for bias L2 sector reuse across heads
    const int smem = (64 * 65 * 3 + 64 * 64 + 64) * (int)sizeof(float);  // ~65 KB
    cudaFuncSetAttribute(attn_kernel, cudaFuncAttributeMaxDynamicSharedMemorySize, smem);
    attn_kernel<<<dim3(NUM_H, NUM_N / 64, NUM_B), 256, smem>>>(sb, mask);

    // 3) output projection: 8192 x 512
    out_gemm_kernel<<<dim3(8, 128), 256>>>(Wout, bout, out);
}